// round 8
// baseline (speedup 1.0000x reference)
#include <cuda_runtime.h>

#define NROWS   512      // 16 * 32
#define NP      256      // particles per row
#define OD      10       // OBS_DIM
#define AD      4        // ACTION_DIM
#define ROW_LEN 2564
#define NBLK    1024     // (row, dir) blocks

__device__ float g_partial[NBLK];
__device__ float g_action[NROWS];
__device__ float g_a0[NROWS];
__device__ int   g_cnt;          // zero-init; last block resets it each run

typedef unsigned long long ull;

__device__ __forceinline__ ull pk2(float a, float b) {
    ull r; asm("mov.b64 %0, {%1, %2};" : "=l"(r) : "f"(a), "f"(b)); return r;
}
__device__ __forceinline__ ull add2_(ull a, ull b) {
    ull r; asm("add.rn.f32x2 %0, %1, %2;" : "=l"(r) : "l"(a), "l"(b)); return r;
}
__device__ __forceinline__ ull fma2_(ull a, ull b, ull c) {
    ull r; asm("fma.rn.f32x2 %0, %1, %2, %3;" : "=l"(r) : "l"(a), "l"(b), "l"(c)); return r;
}
__device__ __forceinline__ unsigned umin_(unsigned a, unsigned b) { return a < b ? a : b; }

__global__ __launch_bounds__(256, 7)
void chamfer_kernel(const float* __restrict__ preds,
                    const float* __restrict__ targ,
                    float* __restrict__ out) {
    const int blk = blockIdx.x;
    const int r   = blk >> 1;        // row = b*32 + h
    const int dir = blk & 1;         // 0: scan obs / query targ (idx1, w=3), 1: scan targ / query obs
    const int t   = threadIdx.x;     // query column q = t  (0..255)

    __shared__ float obs_s[NP * OD];        // 10 KB
    __shared__ float obt_s[NP * OD];        // 10 KB
    __shared__ ulonglong2 sxy[NP / 2];      // packed (x-pair, y-pair)  2 KB
    __shared__ ulonglong2 szw[NP / 2];      // packed (z-pair, w-pair)  2 KB
    __shared__ float4     hn4s[NP / 4];     // biased half-norms, 4/vec 1 KB
    __shared__ float red[256];
    __shared__ int s_last;

    // ---- stage both rows (float4: base (r*2564+4)*4 is 16B-aligned) ----
    const float4* pr4 = (const float4*)(preds + (size_t)r * ROW_LEN + AD);
    const float4* tg4 = (const float4*)(targ  + (size_t)r * ROW_LEN + AD);
    #pragma unroll
    for (int i = t; i < NP * OD / 4; i += 256) {
        ((float4*)obs_s)[i] = pr4[i];
        ((float4*)obt_s)[i] = tg4[i];
    }
    __syncthreads();

    const float* scan = dir ? obt_s : obs_s;   // side we argmin over (candidates)
    const float* mine = dir ? obs_s : obt_s;   // side providing the query column

    // ---- pack candidates: biased half-norm per thread, feature pairs for t<128 ----
    {
        float cx = scan[t*OD+5], cy = scan[t*OD+6], cz = scan[t*OD+7], cw = scan[t*OD+8];
        ((float*)hn4s)[t] = 1.0f + 0.5f * (cx*cx + cy*cy + cz*cz + cw*cw);
    }
    if (t < NP / 2) {
        const int k0 = 2 * t, k1 = 2 * t + 1;
        float x0 = scan[k0*OD+5], y0 = scan[k0*OD+6], z0 = scan[k0*OD+7], w0 = scan[k0*OD+8];
        float x1 = scan[k1*OD+5], y1 = scan[k1*OD+6], z1 = scan[k1*OD+7], w1 = scan[k1*OD+8];
        sxy[t] = make_ulonglong2(pk2(x0, x1), pk2(y0, y1));
        szw[t] = make_ulonglong2(pk2(z0, z1), pk2(w0, w1));
    }
    __syncthreads();

    // ---- this thread's query features ----
    const float ax = mine[t*OD+5], ay = mine[t*OD+6], az = mine[t*OD+7], aw = mine[t*OD+8];
    const ull nAx = pk2(-ax, -ax), nAy = pk2(-ay, -ay), nAz = pk2(-az, -az), nAw = pk2(-aw, -aw);
    const float hA = 0.5f * (ax*ax + ay*ay + az*az + aw*aw);
    const ull baseA = pk2(hA, hA);

    // score = 1 + halfnorm(s) + halfnorm(q) - s.q  (monotone in sq-dist, >= 1 -> sign bit 0)
    // key = (score_bits & ~0xFF) | k  -> unsigned min = first-occurrence argmin
    unsigned bestA = 0xFFFFFFFFu;
    #pragma unroll 2
    for (int kk = 0; kk < NP / 4; ++kk) {
        // 4 candidates per iteration: 4kk .. 4kk+3
        const ulonglong2 xy0 = sxy[2*kk];
        const ulonglong2 xy1 = sxy[2*kk + 1];
        const ulonglong2 zw0 = szw[2*kk];
        const ulonglong2 zw1 = szw[2*kk + 1];
        const float4 h4 = hn4s[kk];
        const ull hlo = pk2(h4.x, h4.y);
        const ull hhi = pk2(h4.z, h4.w);

        // two independent half-chains per pair (depth 3), merged once
        ull u0 = fma2_(xy0.x, nAx, baseA);
        ull v0 = fma2_(zw0.x, nAz, hlo);
        u0 = fma2_(xy0.y, nAy, u0);
        v0 = fma2_(zw0.y, nAw, v0);
        const ull s0 = add2_(u0, v0);

        ull u1 = fma2_(xy1.x, nAx, baseA);
        ull v1 = fma2_(zw1.x, nAz, hhi);
        u1 = fma2_(xy1.y, nAy, u1);
        v1 = fma2_(zw1.y, nAw, v1);
        const ull s1 = add2_(u1, v1);

        const unsigned kb = 4u * kk;
        bestA = umin_(bestA, ((unsigned)s0         & 0xFFFFFF00u) | kb);
        bestA = umin_(bestA, ((unsigned)(s0 >> 32) & 0xFFFFFF00u) | (kb + 1u));
        bestA = umin_(bestA, ((unsigned)s1         & 0xFFFFFF00u) | (kb + 2u));
        bestA = umin_(bestA, ((unsigned)(s1 >> 32) & 0xFFFFFF00u) | (kb + 3u));
    }
    const int iA = bestA & 0xFF;

    // ---- L1 gather over all 10 dims (both rows in smem) ----
    float s1 = 0.f;
    #pragma unroll
    for (int d = 0; d < OD; ++d)
        s1 += fabsf(scan[iA * OD + d] - mine[t * OD + d]);
    const float w = dir ? 1.0f : 3.0f;   // TARGET_WEIGHT on the idx1 direction
    red[t] = w * s1;
    __syncthreads();
    #pragma unroll
    for (int off = 128; off > 0; off >>= 1) {
        if (t < off) red[t] += red[t + off];
        __syncthreads();
    }

    if (t == 0) {
        g_partial[blk] = red[0];
        if (dir == 0) {
            const float* pr = preds + (size_t)r * ROW_LEN;
            const float* tg = targ  + (size_t)r * ROW_LEN;
            float al1 = 0.f;
            #pragma unroll
            for (int d = 0; d < AD; ++d) al1 += fabsf(pr[d] - tg[d]);
            al1 *= 0.25f;
            const int h = r & 31;
            g_action[r] = (h == 1) ? al1 * 10.0f : al1;
            g_a0[r]     = (h == 1) ? al1 : 0.0f;
        }
        __threadfence();
        const int ticket = atomicAdd(&g_cnt, 1);
        s_last = (ticket == NBLK - 1) ? 1 : 0;
    }
    __syncthreads();

    // ---- fused final reduction: last block to finish does it ----
    if (s_last) {
        float c = 0.f;
        for (int i = t; i < NBLK; i += 256) c += g_partial[i];
        red[t] = c;
        __syncthreads();
        #pragma unroll
        for (int off = 128; off > 0; off >>= 1) {
            if (t < off) red[t] += red[t + off];
            __syncthreads();
        }
        const float chamfer_total = red[0];
        __syncthreads();

        float a = (t < NROWS) ? g_action[t] + g_action[t + 256] : 0.f;
        red[t] = a;
        __syncthreads();
        #pragma unroll
        for (int off = 128; off > 0; off >>= 1) {
            if (t < off) red[t] += red[t + off];
            __syncthreads();
        }
        const float action_total = red[0];
        __syncthreads();

        float z = (t < NROWS) ? g_a0[t] + g_a0[t + 256] : 0.f;
        red[t] = z;
        __syncthreads();
        #pragma unroll
        for (int off = 128; off > 0; off >>= 1) {
            if (t < off) red[t] += red[t + off];
            __syncthreads();
        }
        const float a0_total = red[0];

        if (t == 0) {
            // chamfer mean = total / (4 * 512*256*10)
            out[0] = action_total * (1.0f / NROWS) + chamfer_total * (1.0f / 5242880.0f);
            out[1] = a0_total * (1.0f / 16.0f);
            g_cnt  = 0;   // reset for next graph replay
        }
    }
}

extern "C" void kernel_launch(void* const* d_in, const int* in_sizes, int n_in,
                              void* d_out, int out_size) {
    const float* preds = (const float*)d_in[0];
    const float* targ  = (const float*)d_in[1];
    chamfer_kernel<<<NBLK, 256>>>(preds, targ, (float*)d_out);
}